// round 10
// baseline (speedup 1.0000x reference)
#include <cuda_runtime.h>
#include <math.h>

// ---------------------------------------------------------------------------
// FocalLoss (RetinaNet-style) on GB300 — single-wave fused kernel.
//   occ=4 CTAs/SM, grid = one wave (~4*152 blocks), contiguous chunks,
//   MLP_p1=4 front-batched loads: oe*MLP_p1 = 16 = L1tex-queue threshold
//   (B300 cross-CTA contention model) -> minimal CTA spread + high in-flight.
//  Part 1 (match, grid-stride over anchors):
//      matched  -> reg smooth-L1, count, gt-element pos-correction
//      deadzone -> cancel own clf row's stream contribution (exact formula)
//  Part 2 (stream): acc += pm^2*log2(1-pm), pm=min(p,1-eps); scale -.75*ln2.
//  Part 3: ticket; last block finalizes outputs and resets state.
// Inputs (metadata order):
//   d_in[0] classifications float32 [B, A, C]
//   d_in[1] regressions     float32 [B, A, 4]
//   d_in[2] anchors         float32 [1, A, 4]   (y1, x1, y2, x2)
//   d_in[3] annotations     float32 [B, M, 5]   (x1, y1, x2, y2, label)
// Output: float32 [2] = (clf_loss_weighted, reg_loss_weighted)
// ---------------------------------------------------------------------------

#define FL_EPS    1e-4f
#define MAX_B     16
#define MAX_M     128
#define LN2_D     0.693147180559945309
#define THREADS   256

__device__ double g_clf_sum[MAX_B];
__device__ double g_sl1_sum[MAX_B];
__device__ int    g_nm[MAX_B];
__device__ unsigned int g_ticket;    // zero-init; self-resetting each replay

// identical per-element core used by stream AND all corrections.
// fl_core(0) == 0 exactly, so zero-padded guard loads are harmless.
__device__ __forceinline__ float fl_core(float p) {
    const float pm = fminf(p, 1.0f - FL_EPS);
    return pm * pm * __log2f(1.0f - pm);      // negative
}

__global__ __launch_bounds__(THREADS, 4)
void fl_fused_kernel(const float4* __restrict__ clf4,
                     const float*  __restrict__ clf,
                     const float4* __restrict__ reg,
                     const float4* __restrict__ anc,
                     const float*  __restrict__ ann,
                     float* __restrict__ out,
                     int A, int C, int B, int M, int perImgV4) {
    const int b = blockIdx.y;

    __shared__ float  s_raw[MAX_M * 5];
    __shared__ float  s_bx1[MAX_M], s_by1[MAX_M], s_bx2[MAX_M], s_by2[MAX_M];
    __shared__ float  s_bar[MAX_M], s_lbl[MAX_M];
    __shared__ int    s_nv;
    __shared__ double s_sl1, s_cor, s_acc;
    __shared__ int    s_nm;
    __shared__ bool   s_last;

    if (threadIdx.x == 0) { s_sl1 = 0.0; s_cor = 0.0; s_acc = 0.0; s_nm = 0; }
    {
        const int annN = M * 5;
        for (int i = threadIdx.x; i < annN; i += blockDim.x)
            s_raw[i] = ann[(size_t)b * annN + i];
    }
    __syncthreads();
    if (threadIdx.x == 0) {
        int nv = 0;
        for (int j = 0; j < M; j++) {
            const float lbl = s_raw[j * 5 + 4];
            if (lbl == -1.0f) continue;             // order preserved -> tiebreak ok
            s_bx1[nv] = s_raw[j * 5 + 0];
            s_by1[nv] = s_raw[j * 5 + 1];
            s_bx2[nv] = s_raw[j * 5 + 2];
            s_by2[nv] = s_raw[j * 5 + 3];
            s_bar[nv] = (s_bx2[nv] - s_bx1[nv]) * (s_by2[nv] - s_by1[nv]);
            s_lbl[nv] = lbl;
            nv++;
        }
        s_nv = nv;
    }
    __syncthreads();

    // ============== Part 1: matching (grid-stride over anchors) ============
    {
        const int tstride = gridDim.x * blockDim.x;
        const int nv = s_nv;
        for (int a = blockIdx.x * blockDim.x + threadIdx.x; a < A; a += tstride) {
            const float4 av = anc[a];            // y1, x1, y2, x2
            const float ay1 = av.x, ax1 = av.y, ay2 = av.z, ax2 = av.w;
            const float aarea = (ax2 - ax1) * (ay2 - ay1);

            // division-free argmax over valid boxes (first-index tiebreak)
            float bestI = 0.0f, bestU = 1.0f;
            int   idx = -1;
            for (int j = 0; j < nv; j++) {
                float iw = fminf(ax2, s_bx2[j]) - fmaxf(ax1, s_bx1[j]); iw = fmaxf(iw, 0.0f);
                float ih = fminf(ay2, s_by2[j]) - fmaxf(ay1, s_by1[j]); ih = fmaxf(ih, 0.0f);
                const float inter = iw * ih;
                const float uni = fmaxf(aarea + s_bar[j] - inter, 1e-8f);
                if (idx < 0) { bestI = inter; bestU = uni; idx = j; }
                else if (inter * bestU > bestI * uni) { bestI = inter; bestU = uni; idx = j; }
            }
            const float v = (idx >= 0) ? (bestI / bestU) : -1.0f;
            const bool matched   = v > 0.5f;
            const bool unmatched = v < 0.4f;

            if (!matched && !unmatched) {
                // dead-zone: cancel this row's stream contribution
                const float* row = clf + ((size_t)b * A + a) * C;
                float s = 0.0f;
                for (int c = 0; c < C; c++) s += fl_core(row[c]);
                atomicAdd(&s_cor, (double)s * (0.75 * LN2_D));
            } else if (matched) {
                // gt-element correction: replace stream's neg term by pos term
                const int gt = (int)s_lbl[idx] - 1;
                const float p = clf[((size_t)b * A + a) * C + gt];
                const float pc = fminf(fmaxf(p, FL_EPS), 1.0f - FL_EPS);
                const float om = 1.0f - pc;
                const double pos = (double)(0.25f * om * om * (-__logf(pc)));
                const double st  = (double)fl_core(p) * (-0.75 * LN2_D);
                atomicAdd(&s_cor, pos - st);

                // regression smooth-L1
                const float gx1 = s_bx1[idx], gy1 = s_by1[idx];
                const float gx2 = s_bx2[idx], gy2 = s_by2[idx];
                const float gwr = gx2 - gx1, ghr = gy2 - gy1;
                const float gcx = gx1 + 0.5f * gwr, gcy = gy1 + 0.5f * ghr;
                const float gw = fmaxf(gwr, 1.0f),  gh = fmaxf(ghr, 1.0f);
                const float aw = ax2 - ax1, ah = ay2 - ay1;
                const float acx = ax1 + 0.5f * aw, acy = ay1 + 0.5f * ah;
                const float4 rv = reg[(size_t)b * A + a];
                float s = 0.0f;
                float d;
                d = fabsf(9.0f * (rv.x - (gcy - acy) / ah));
                s += (d < 1.0f) ? 0.5f * d * d : (d - 0.5f);
                d = fabsf(9.0f * (rv.y - (gcx - acx) / aw));
                s += (d < 1.0f) ? 0.5f * d * d : (d - 0.5f);
                d = fabsf(9.0f * (rv.z - __logf(gh / ah)));
                s += (d < 1.0f) ? 0.5f * d * d : (d - 0.5f);
                d = fabsf(9.0f * (rv.w - __logf(gw / aw)));
                s += (d < 1.0f) ? 0.5f * d * d : (d - 0.5f);
                atomicAdd(&s_sl1, (double)s);
                atomicAdd(&s_nm, 1);
            }
        }
    }

    // ========= Part 2: contiguous-chunk stream, MLP_p1 = 4 =================
    {
        const float4* base = clf4 + (size_t)b * perImgV4;
        const int chunk = (perImgV4 + gridDim.x - 1) / gridDim.x;
        const int start = blockIdx.x * chunk;
        const int end   = min(start + chunk, perImgV4);
        const float4 z = make_float4(0.0f, 0.0f, 0.0f, 0.0f);

        float acc0 = 0.0f, acc1 = 0.0f;
        for (int i = start + threadIdx.x; i < end; i += 4 * THREADS) {
            const int i1 = i + THREADS;
            const int i2 = i + 2 * THREADS;
            const int i3 = i + 3 * THREADS;
            // 4 front-batched independent loads (consecutive in SASS)
            const float4 v0 = base[i];
            const float4 v1 = (i1 < end) ? base[i1] : z;
            const float4 v2 = (i2 < end) ? base[i2] : z;
            const float4 v3 = (i3 < end) ? base[i3] : z;
            acc0 += fl_core(v0.x) + fl_core(v0.y);
            acc1 += fl_core(v0.z) + fl_core(v0.w);
            acc0 += fl_core(v1.x) + fl_core(v1.y);
            acc1 += fl_core(v1.z) + fl_core(v1.w);
            acc0 += fl_core(v2.x) + fl_core(v2.y);
            acc1 += fl_core(v2.z) + fl_core(v2.w);
            acc0 += fl_core(v3.x) + fl_core(v3.y);
            acc1 += fl_core(v3.z) + fl_core(v3.w);
        }
        float acc = acc0 + acc1;
        if (blockIdx.x == 0 && threadIdx.x == 0) {     // scalar tail, if any
            for (int e = perImgV4 * 4; e < A * C; e++)
                acc += fl_core(clf[(size_t)b * A * C + e]);
        }
        #pragma unroll
        for (int off = 16; off; off >>= 1)
            acc += __shfl_xor_sync(0xffffffffu, acc, off);
        if ((threadIdx.x & 31) == 0)
            atomicAdd(&s_acc, (double)acc);
    }
    __syncthreads();

    // ======================= Part 3: accumulate + finalize =================
    if (threadIdx.x == 0) {
        const double clfAdd = s_acc * (-0.75 * LN2_D) + s_cor;
        if (clfAdd != 0.0) atomicAdd(&g_clf_sum[b], clfAdd);
        if (s_sl1 != 0.0)  atomicAdd(&g_sl1_sum[b], s_sl1);
        if (s_nm)          atomicAdd(&g_nm[b], s_nm);
        __threadfence();
        const unsigned int total = gridDim.x * gridDim.y;
        const unsigned int t = atomicAdd(&g_ticket, 1u);
        s_last = (t == total - 1u);
    }
    __syncthreads();

    if (s_last && threadIdx.x == 0) {
        __threadfence();
        double cl = 0.0, rl = 0.0;
        for (int bb = 0; bb < B; bb++) {
            const int nm = g_nm[bb];
            const int dn = nm > 1 ? nm : 1;
            cl += g_clf_sum[bb] / (double)dn;
            if (nm > 0) rl += g_sl1_sum[bb] / (double)(4 * nm);
            g_clf_sum[bb] = 0.0;
            g_sl1_sum[bb] = 0.0;
            g_nm[bb]      = 0;
        }
        out[0] = (float)(cl / (double)B);          // CLF_W = 1.0
        out[1] = (float)(50.0 * rl / (double)B);   // REG_W = 50.0
        g_ticket = 0u;
    }
}

extern "C" void kernel_launch(void* const* d_in, const int* in_sizes, int n_in,
                              void* d_out, int out_size) {
    const float* clf = (const float*)d_in[0];
    const float* reg = (const float*)d_in[1];
    const float* anc = (const float*)d_in[2];
    const float* ann = (const float*)d_in[3];
    float* out = (float*)d_out;

    const int A = in_sizes[2] / 4;                       // anchors: 1*A*4
    const int B = in_sizes[1] / (4 * A);                 // regressions: B*A*4
    const int C = (int)((long long)in_sizes[0] / ((long long)B * A)); // B*A*C
    const int M = in_sizes[3] / (5 * B);                 // annotations: B*M*5

    const int perImgV4 = (A * C) / 4;
    // one wave: ~4 CTAs/SM on 152 SMs, split across B images
    int blocksX = (4 * 152) / (B > 0 ? B : 1);
    if (blocksX < 1) blocksX = 1;
    if (blocksX > perImgV4) blocksX = perImgV4 > 0 ? perImgV4 : 1;
    dim3 grid(blocksX, B);
    fl_fused_kernel<<<grid, THREADS>>>((const float4*)clf, clf,
                                       (const float4*)reg, (const float4*)anc,
                                       ann, out, A, C, B, M, perImgV4);
}

// round 11
// speedup vs baseline: 1.0616x; 1.0616x over previous
#include <cuda_runtime.h>
#include <math.h>
#include <stdint.h>

// ---------------------------------------------------------------------------
// FocalLoss (RetinaNet-style) on GB300 — fused kernel with cp.async.bulk
// (TMA-path) double-buffered streaming.
//   Prologue: issue bulk copies of tiles 0,1 (20KB each) into SMEM.
//   Part 1  : matching (grid-stride over anchors) — hides under DMA:
//               matched  -> reg smooth-L1, count, gt-element pos-correction
//               deadzone -> cancel own clf row's stream contribution
//   Part 2  : pipeline — wait mbarrier, compute tile from SMEM, sync,
//             re-issue next tile into the freed buffer.
//               acc += pm^2*log2(1-pm), pm=min(p,1-eps); scale -0.75*ln2.
//   Part 3  : ticket; last block finalizes outputs and resets state.
// Inputs (metadata order):
//   d_in[0] classifications float32 [B, A, C]
//   d_in[1] regressions     float32 [B, A, 4]
//   d_in[2] anchors         float32 [1, A, 4]   (y1, x1, y2, x2)
//   d_in[3] annotations     float32 [B, M, 5]   (x1, y1, x2, y2, label)
// Output: float32 [2] = (clf_loss_weighted, reg_loss_weighted)
// ---------------------------------------------------------------------------

#define FL_EPS    1e-4f
#define MAX_B     16
#define MAX_M     128
#define LN2_D     0.693147180559945309
#define THREADS   256
#define TILE_V4   1280               // float4 per tile = 20 KB

__device__ double g_clf_sum[MAX_B];
__device__ double g_sl1_sum[MAX_B];
__device__ int    g_nm[MAX_B];
__device__ unsigned int g_ticket;    // zero-init; self-resetting each replay

// identical per-element core used by stream AND all corrections
__device__ __forceinline__ float fl_core(float p) {
    const float pm = fminf(p, 1.0f - FL_EPS);
    return pm * pm * __log2f(1.0f - pm);      // negative
}

__device__ __forceinline__ uint32_t smem_u32(const void* p) {
    return (uint32_t)__cvta_generic_to_shared(p);
}

#define MBAR_INIT(addr, cnt) \
    asm volatile("mbarrier.init.shared.b64 [%0], %1;" :: "r"(addr), "r"(cnt) : "memory")

#define MBAR_EXPECT_TX(addr, bytes) \
    asm volatile("mbarrier.arrive.expect_tx.shared.b64 _, [%0], %1;" \
                 :: "r"(addr), "r"(bytes) : "memory")

#define BULK_G2S(dst_smem, src_gmem, bytes, mbar) \
    asm volatile("cp.async.bulk.shared::cta.global.mbarrier::complete_tx::bytes " \
                 "[%0], [%1], %2, [%3];" \
                 :: "r"(dst_smem), "l"(src_gmem), "r"(bytes), "r"(mbar) : "memory")

#define MBAR_WAIT(addr, ph) do { \
    asm volatile("{\n\t.reg .pred P1;\n\t" \
        "WAIT_LOOP_%=:\n\t" \
        "mbarrier.try_wait.parity.acquire.cta.shared::cta.b64 P1, [%0], %1, 0x989680;\n\t" \
        "@P1 bra.uni WAIT_DONE_%=;\n\t" \
        "bra.uni WAIT_LOOP_%=;\n\t" \
        "WAIT_DONE_%=:\n\t}" \
        :: "r"(addr), "r"(ph) : "memory"); \
} while (0)

__global__ __launch_bounds__(THREADS)
void fl_fused_kernel(const float4* __restrict__ clf4,
                     const float*  __restrict__ clf,
                     const float4* __restrict__ reg,
                     const float4* __restrict__ anc,
                     const float*  __restrict__ ann,
                     float* __restrict__ out,
                     int A, int C, int B, int M, int perImgV4) {
    const int b = blockIdx.y;

    __shared__ __align__(16) float4 s_buf0[TILE_V4];
    __shared__ __align__(16) float4 s_buf1[TILE_V4];
    __shared__ __align__(8)  unsigned long long s_mbar[2];
    __shared__ float  s_raw[MAX_M * 5];
    __shared__ float  s_bx1[MAX_M], s_by1[MAX_M], s_bx2[MAX_M], s_by2[MAX_M];
    __shared__ float  s_bar[MAX_M], s_lbl[MAX_M];
    __shared__ int    s_nv;
    __shared__ double s_sl1, s_cor, s_acc;
    __shared__ int    s_nm;
    __shared__ bool   s_last;

    // ---- block's contiguous chunk of this image's clf tensor -------------
    const char* gsrc = (const char*)(clf4 + (size_t)b * perImgV4);
    const int chunk   = (perImgV4 + gridDim.x - 1) / gridDim.x;
    const int startV4 = blockIdx.x * chunk;
    const int endV4   = min(startV4 + chunk, perImgV4);
    const int nV4     = endV4 > startV4 ? endV4 - startV4 : 0;
    const int ntb     = (nV4 + TILE_V4 - 1) / TILE_V4;

    const uint32_t mb0 = smem_u32(&s_mbar[0]);
    const uint32_t mb1 = smem_u32(&s_mbar[1]);
    const uint32_t sb0 = smem_u32(s_buf0);
    const uint32_t sb1 = smem_u32(s_buf1);

    if (threadIdx.x == 0) {
        s_sl1 = 0.0; s_cor = 0.0; s_acc = 0.0; s_nm = 0;
        MBAR_INIT(mb0, 1);
        MBAR_INIT(mb1, 1);
    }
    {   // annotations -> smem (overlappable with nothing yet; cheap)
        const int annN = M * 5;
        for (int i = threadIdx.x; i < annN; i += blockDim.x)
            s_raw[i] = ann[(size_t)b * annN + i];
    }
    __syncthreads();      // mbarrier init + s_raw visible

    // ---- prologue: issue first two tiles; DMA overlaps matching ----------
    if (threadIdx.x == 0) {
        if (ntb > 0) {
            const uint32_t bytes = (uint32_t)min(TILE_V4, nV4) * 16u;
            MBAR_EXPECT_TX(mb0, bytes);
            BULK_G2S(sb0, gsrc + (size_t)startV4 * 16, bytes, mb0);
        }
        if (ntb > 1) {
            const uint32_t bytes = (uint32_t)min(TILE_V4, nV4 - TILE_V4) * 16u;
            MBAR_EXPECT_TX(mb1, bytes);
            BULK_G2S(sb1, gsrc + (size_t)(startV4 + TILE_V4) * 16, bytes, mb1);
        }
    }

    // ---- compact valid boxes (thread 0) -----------------------------------
    if (threadIdx.x == 0) {
        int nv = 0;
        for (int j = 0; j < M; j++) {
            const float lbl = s_raw[j * 5 + 4];
            if (lbl == -1.0f) continue;             // order preserved -> tiebreak ok
            s_bx1[nv] = s_raw[j * 5 + 0];
            s_by1[nv] = s_raw[j * 5 + 1];
            s_bx2[nv] = s_raw[j * 5 + 2];
            s_by2[nv] = s_raw[j * 5 + 3];
            s_bar[nv] = (s_bx2[nv] - s_bx1[nv]) * (s_by2[nv] - s_by1[nv]);
            s_lbl[nv] = lbl;
            nv++;
        }
        s_nv = nv;
    }
    __syncthreads();

    // ============== Part 1: matching (grid-stride over anchors) ============
    {
        const int tstride = gridDim.x * blockDim.x;
        const int nv = s_nv;
        for (int a = blockIdx.x * blockDim.x + threadIdx.x; a < A; a += tstride) {
            const float4 av = anc[a];            // y1, x1, y2, x2
            const float ay1 = av.x, ax1 = av.y, ay2 = av.z, ax2 = av.w;
            const float aarea = (ax2 - ax1) * (ay2 - ay1);

            // division-free argmax over valid boxes (first-index tiebreak)
            float bestI = 0.0f, bestU = 1.0f;
            int   idx = -1;
            for (int j = 0; j < nv; j++) {
                float iw = fminf(ax2, s_bx2[j]) - fmaxf(ax1, s_bx1[j]); iw = fmaxf(iw, 0.0f);
                float ih = fminf(ay2, s_by2[j]) - fmaxf(ay1, s_by1[j]); ih = fmaxf(ih, 0.0f);
                const float inter = iw * ih;
                const float uni = fmaxf(aarea + s_bar[j] - inter, 1e-8f);
                if (idx < 0) { bestI = inter; bestU = uni; idx = j; }
                else if (inter * bestU > bestI * uni) { bestI = inter; bestU = uni; idx = j; }
            }
            const float v = (idx >= 0) ? (bestI / bestU) : -1.0f;
            const bool matched   = v > 0.5f;
            const bool unmatched = v < 0.4f;

            if (!matched && !unmatched) {
                // dead-zone: cancel this row's stream contribution
                const float* row = clf + ((size_t)b * A + a) * C;
                float s = 0.0f;
                for (int c = 0; c < C; c++) s += fl_core(row[c]);
                atomicAdd(&s_cor, (double)s * (0.75 * LN2_D));
            } else if (matched) {
                // gt-element correction: replace stream's neg term by pos term
                const int gt = (int)s_lbl[idx] - 1;
                const float p = clf[((size_t)b * A + a) * C + gt];
                const float pc = fminf(fmaxf(p, FL_EPS), 1.0f - FL_EPS);
                const float om = 1.0f - pc;
                const double pos = (double)(0.25f * om * om * (-__logf(pc)));
                const double st  = (double)fl_core(p) * (-0.75 * LN2_D);
                atomicAdd(&s_cor, pos - st);

                // regression smooth-L1
                const float gx1 = s_bx1[idx], gy1 = s_by1[idx];
                const float gx2 = s_bx2[idx], gy2 = s_by2[idx];
                const float gwr = gx2 - gx1, ghr = gy2 - gy1;
                const float gcx = gx1 + 0.5f * gwr, gcy = gy1 + 0.5f * ghr;
                const float gw = fmaxf(gwr, 1.0f),  gh = fmaxf(ghr, 1.0f);
                const float aw = ax2 - ax1, ah = ay2 - ay1;
                const float acx = ax1 + 0.5f * aw, acy = ay1 + 0.5f * ah;
                const float4 rv = reg[(size_t)b * A + a];
                float s = 0.0f;
                float d;
                d = fabsf(9.0f * (rv.x - (gcy - acy) / ah));
                s += (d < 1.0f) ? 0.5f * d * d : (d - 0.5f);
                d = fabsf(9.0f * (rv.y - (gcx - acx) / aw));
                s += (d < 1.0f) ? 0.5f * d * d : (d - 0.5f);
                d = fabsf(9.0f * (rv.z - __logf(gh / ah)));
                s += (d < 1.0f) ? 0.5f * d * d : (d - 0.5f);
                d = fabsf(9.0f * (rv.w - __logf(gw / aw)));
                s += (d < 1.0f) ? 0.5f * d * d : (d - 0.5f);
                atomicAdd(&s_sl1, (double)s);
                atomicAdd(&s_nm, 1);
            }
        }
    }

    // ============== Part 2: double-buffered SMEM pipeline ==================
    {
        float acc0 = 0.0f, acc1 = 0.0f;
        int ph0 = 0, ph1 = 0;
        for (int t = 0; t < ntb; t++) {
            const int tsV4  = startV4 + t * TILE_V4;
            const int count = min(TILE_V4, endV4 - tsV4);
            const float4* sb;
            if ((t & 1) == 0) { MBAR_WAIT(mb0, ph0); ph0 ^= 1; sb = s_buf0; }
            else              { MBAR_WAIT(mb1, ph1); ph1 ^= 1; sb = s_buf1; }

            for (int k = threadIdx.x; k < count; k += THREADS) {
                const float4 v = sb[k];
                acc0 += fl_core(v.x) + fl_core(v.y);
                acc1 += fl_core(v.z) + fl_core(v.w);
            }
            __syncthreads();          // all reads of this buffer done

            const int nt = t + 2;
            if (threadIdx.x == 0 && nt < ntb) {
                const int ntsV4 = startV4 + nt * TILE_V4;
                const uint32_t bytes = (uint32_t)min(TILE_V4, endV4 - ntsV4) * 16u;
                const uint32_t mb = ((t & 1) == 0) ? mb0 : mb1;
                const uint32_t db = ((t & 1) == 0) ? sb0 : sb1;
                MBAR_EXPECT_TX(mb, bytes);
                BULK_G2S(db, gsrc + (size_t)ntsV4 * 16, bytes, mb);
            }
        }
        float acc = acc0 + acc1;
        if (blockIdx.x == 0 && threadIdx.x == 0) {     // scalar tail, if any
            for (int e = perImgV4 * 4; e < A * C; e++)
                acc += fl_core(clf[(size_t)b * A * C + e]);
        }
        #pragma unroll
        for (int off = 16; off; off >>= 1)
            acc += __shfl_xor_sync(0xffffffffu, acc, off);
        if ((threadIdx.x & 31) == 0)
            atomicAdd(&s_acc, (double)acc);
    }
    __syncthreads();

    // ======================= Part 3: accumulate + finalize =================
    if (threadIdx.x == 0) {
        const double clfAdd = s_acc * (-0.75 * LN2_D) + s_cor;
        if (clfAdd != 0.0) atomicAdd(&g_clf_sum[b], clfAdd);
        if (s_sl1 != 0.0)  atomicAdd(&g_sl1_sum[b], s_sl1);
        if (s_nm)          atomicAdd(&g_nm[b], s_nm);
        __threadfence();
        const unsigned int total = gridDim.x * gridDim.y;
        const unsigned int t = atomicAdd(&g_ticket, 1u);
        s_last = (t == total - 1u);
    }
    __syncthreads();

    if (s_last && threadIdx.x == 0) {
        __threadfence();
        double cl = 0.0, rl = 0.0;
        for (int bb = 0; bb < B; bb++) {
            const int nm = g_nm[bb];
            const int dn = nm > 1 ? nm : 1;
            cl += g_clf_sum[bb] / (double)dn;
            if (nm > 0) rl += g_sl1_sum[bb] / (double)(4 * nm);
            g_clf_sum[bb] = 0.0;
            g_sl1_sum[bb] = 0.0;
            g_nm[bb]      = 0;
        }
        out[0] = (float)(cl / (double)B);          // CLF_W = 1.0
        out[1] = (float)(50.0 * rl / (double)B);   // REG_W = 50.0
        g_ticket = 0u;
    }
}

extern "C" void kernel_launch(void* const* d_in, const int* in_sizes, int n_in,
                              void* d_out, int out_size) {
    const float* clf = (const float*)d_in[0];
    const float* reg = (const float*)d_in[1];
    const float* anc = (const float*)d_in[2];
    const float* ann = (const float*)d_in[3];
    float* out = (float*)d_out;

    const int A = in_sizes[2] / 4;                       // anchors: 1*A*4
    const int B = in_sizes[1] / (4 * A);                 // regressions: B*A*4
    const int C = (int)((long long)in_sizes[0] / ((long long)B * A)); // B*A*C
    const int M = in_sizes[3] / (5 * B);                 // annotations: B*M*5

    const int perImgV4 = (A * C) / 4;
    // one wave at ~4 CTAs/SM on 152 SMs, split across B images
    int blocksX = (4 * 152) / (B > 0 ? B : 1);
    if (blocksX < 1) blocksX = 1;
    if (blocksX > perImgV4) blocksX = perImgV4 > 0 ? perImgV4 : 1;
    dim3 grid(blocksX, B);
    fl_fused_kernel<<<grid, THREADS>>>((const float4*)clf, clf,
                                       (const float4*)reg, (const float4*)anc,
                                       ann, out, A, C, B, M, perImgV4);
}